// round 16
// baseline (speedup 1.0000x reference)
#include <cuda_runtime.h>

// Problem constants (fixed: B=128, C=1024, N=512, NUM_CLASSES=1024)
#define BB 128
#define CC 1024
#define NN 512
#define NC 1024
#define LCAP 48    // per-category list capacity (mean ~10, 12 sigma headroom)
#define FLAT 16    // flat-load region; tails (~3% of rows) handled scalar
#define INVM 16    // max contributor rows per atom (Poisson(2), P(>16) ~ 0)

// byte offsets into g_mt (row stride = BB*4 = 512 bytes = n<<9)
#define POS_SENT ((NN + 1) << 9)   // row NN+1 = 1.0 -> fmin no-op
#define NEG_SENT (NN << 9)         // row NN   = 0.0 -> fmax no-op

// ---- scratch (device globals; zero-init at load; counters self-reset) ----
__device__ float g_mt[NN + 2][BB];      // rows: 0..511 data, 512 zeros, 513 ones
__device__ int   g_lists[CC][2 * LCAP]; // [0:48) pos offsets, [48:96) neg offsets
__device__ int   g_cnts[CC];            // pc | (nc << 8)
__device__ int   g_inv[NN][INVM];       // contributor rows: (c<<1)|isNeg
__device__ int   g_cd[NN];              // contributor count (node2 resets to 0)

// ============ Node 1: full prep (masks -> lists/inv; transpose; copy) ======
// grid = 512 CTAs x 128 threads; CTA cb handles rows c0=2cb, c1=2cb+1.
__global__ void __launch_bounds__(128) k_prep(
    const float* __restrict__ preds,
    const float* __restrict__ pos_head,
    const float* __restrict__ neg_head,
    const float* __restrict__ pos_body,
    const float* __restrict__ neg_body,
    const int*   __restrict__ atoms,     // jax downcasts int64 -> int32
    float*       __restrict__ out)
{
    const int cb = blockIdx.x;
    const int c0 = cb * 2, c1 = c0 + 1;
    const int t  = threadIdx.x;

    // front-batched independent loads (MLP 8)
    const float4 p0 = ((const float4*)(pos_body + c0 * NN))[t];
    const float4 q0 = ((const float4*)(neg_body + c0 * NN))[t];
    const float4 h0 = ((const float4*)(pos_head + c0 * NN))[t];
    const float4 g0 = ((const float4*)(neg_head + c0 * NN))[t];
    const float4 p1 = ((const float4*)(pos_body + c1 * NN))[t];
    const float4 q1 = ((const float4*)(neg_body + c1 * NN))[t];
    const float4 h1 = ((const float4*)(pos_head + c1 * NN))[t];
    const float4 g1 = ((const float4*)(neg_head + c1 * NN))[t];

    // preds -> out copy: 64 float4 per CTA (threads 0..63 cover all 32768)
    if (t < 64)
        ((float4*)out)[cb * 64 + t] = ((const float4*)preds)[cb * 64 + t];

    // g_mt transpose gather: row n = cb, thread t = batch b
    g_mt[cb][t] = preds[t * NC + (atoms[cb] & (NC - 1))];
    if (cb == 0) g_mt[NN + 1][t] = 1.0f;    // pos-sentinel row (row NN stays 0)

    __shared__ int pc0, nc0, pc1, nc1;
    if (t == 0) { pc0 = 0; nc0 = 0; pc1 = 0; nc1 = 0; }
    __syncthreads();

    const int n0 = t * 4;

    { // row c0 pos
        int loc[4]; int ln = 0;
        if (p0.x > 0.5f) loc[ln++] = (n0 + 0) << 9;
        if (p0.y > 0.5f) loc[ln++] = (n0 + 1) << 9;
        if (p0.z > 0.5f) loc[ln++] = (n0 + 2) << 9;
        if (p0.w > 0.5f) loc[ln++] = (n0 + 3) << 9;
        if (ln) {
            int base = atomicAdd(&pc0, ln);
            #pragma unroll
            for (int i = 0; i < 4; i++)
                if (i < ln && base + i < LCAP) g_lists[c0][base + i] = loc[i];
        }
    }
    { // row c0 neg
        int loc[4]; int ln = 0;
        if (q0.x > 0.5f) loc[ln++] = (n0 + 0) << 9;
        if (q0.y > 0.5f) loc[ln++] = (n0 + 1) << 9;
        if (q0.z > 0.5f) loc[ln++] = (n0 + 2) << 9;
        if (q0.w > 0.5f) loc[ln++] = (n0 + 3) << 9;
        if (ln) {
            int base = atomicAdd(&nc0, ln);
            #pragma unroll
            for (int i = 0; i < 4; i++)
                if (i < ln && base + i < LCAP) g_lists[c0][LCAP + base + i] = loc[i];
        }
    }
    { // row c1 pos
        int loc[4]; int ln = 0;
        if (p1.x > 0.5f) loc[ln++] = (n0 + 0) << 9;
        if (p1.y > 0.5f) loc[ln++] = (n0 + 1) << 9;
        if (p1.z > 0.5f) loc[ln++] = (n0 + 2) << 9;
        if (p1.w > 0.5f) loc[ln++] = (n0 + 3) << 9;
        if (ln) {
            int base = atomicAdd(&pc1, ln);
            #pragma unroll
            for (int i = 0; i < 4; i++)
                if (i < ln && base + i < LCAP) g_lists[c1][base + i] = loc[i];
        }
    }
    { // row c1 neg
        int loc[4]; int ln = 0;
        if (q1.x > 0.5f) loc[ln++] = (n0 + 0) << 9;
        if (q1.y > 0.5f) loc[ln++] = (n0 + 1) << 9;
        if (q1.z > 0.5f) loc[ln++] = (n0 + 2) << 9;
        if (q1.w > 0.5f) loc[ln++] = (n0 + 3) << 9;
        if (ln) {
            int base = atomicAdd(&nc1, ln);
            #pragma unroll
            for (int i = 0; i < 4; i++)
                if (i < ln && base + i < LCAP) g_lists[c1][LCAP + base + i] = loc[i];
        }
    }

    { // head entry row c0 -> inverse map (exactly one nonzero across pos/neg)
        int hm = -1;
        if (h0.x > 0.5f) hm = ((n0 + 0) << 1);
        if (h0.y > 0.5f) hm = ((n0 + 1) << 1);
        if (h0.z > 0.5f) hm = ((n0 + 2) << 1);
        if (h0.w > 0.5f) hm = ((n0 + 3) << 1);
        if (g0.x > 0.5f) hm = ((n0 + 0) << 1) | 1;
        if (g0.y > 0.5f) hm = ((n0 + 1) << 1) | 1;
        if (g0.z > 0.5f) hm = ((n0 + 2) << 1) | 1;
        if (g0.w > 0.5f) hm = ((n0 + 3) << 1) | 1;
        if (hm >= 0) {                        // single finder thread: race-free
            const int nn = (hm >> 1) & (NN - 1);
            const int s  = atomicAdd(&g_cd[nn], 1);
            if (s < INVM) g_inv[nn][s] = (c0 << 1) | (hm & 1);
        }
    }
    { // head entry row c1
        int hm = -1;
        if (h1.x > 0.5f) hm = ((n0 + 0) << 1);
        if (h1.y > 0.5f) hm = ((n0 + 1) << 1);
        if (h1.z > 0.5f) hm = ((n0 + 2) << 1);
        if (h1.w > 0.5f) hm = ((n0 + 3) << 1);
        if (g1.x > 0.5f) hm = ((n0 + 0) << 1) | 1;
        if (g1.y > 0.5f) hm = ((n0 + 1) << 1) | 1;
        if (g1.z > 0.5f) hm = ((n0 + 2) << 1) | 1;
        if (g1.w > 0.5f) hm = ((n0 + 3) << 1) | 1;
        if (hm >= 0) {
            const int nn = (hm >> 1) & (NN - 1);
            const int s  = atomicAdd(&g_cd[nn], 1);
            if (s < INVM) g_inv[nn][s] = (c1 << 1) | (hm & 1);
        }
    }

    __syncthreads();
    const int p0m = min(pc0, LCAP), n0m = min(nc0, LCAP);
    const int p1m = min(pc1, LCAP), n1m = min(nc1, LCAP);

    // sentinel-pad the flat-16 regions
    if (t < FLAT) {
        if (t >= p0m) g_lists[c0][t] = POS_SENT;
    } else if (t < 2 * FLAT) {
        const int j = t - FLAT;
        if (j >= n0m) g_lists[c0][LCAP + j] = NEG_SENT;
    } else if (t < 3 * FLAT) {
        const int j = t - 2 * FLAT;
        if (j >= p1m) g_lists[c1][j] = POS_SENT;
    } else if (t < 4 * FLAT) {
        const int j = t - 3 * FLAT;
        if (j >= n1m) g_lists[c1][LCAP + j] = NEG_SENT;
    }
    if (t == 0)  g_cnts[c0] = p0m | (n0m << 8);
    if (t == 64) g_cnts[c1] = p1m | (n1m << 8);
}

// ============ Node 2: per-atom, contributor-parallel, NO global atomics =====
// grid = 512 CTAs x 512 threads. CTA = atom n. Group g = t>>7 handles
// contributor i0+g; lanes t&127 = batch b. Combine via smem atomicMax
// (128 distinct banks per group -> conflict-free). Finalize in-CTA.
__global__ void __launch_bounds__(512) k_atoms(
    const int* __restrict__ atoms,
    float*     __restrict__ out)
{
    const int n   = blockIdx.x;
    const int t   = threadIdx.x;
    const int b   = t & 127;
    const int grp = t >> 7;

    __shared__ unsigned lb_s[BB], ub_s[BB];
    __shared__ int s_cn;

    // hoisted independent loads (round 1)
    const int col = atoms[n] & (NC - 1);          // uniform
    float mval = 0.0f;
    if (t < BB) { mval = g_mt[n][t]; lb_s[t] = 0u; ub_s[t] = 0u; }
    if (t == 0) { s_cn = g_cd[n]; g_cd[n] = 0; }  // read + replay-safe reset
    __syncthreads();

    const int cn = min(s_cn, INVM);
    const char* mtb = (const char*)&g_mt[0][0] + b * 4;

    for (int i0 = 0; i0 < cn; i0 += 4) {
        const int i = i0 + grp;
        if (i < cn) {
            const int ent  = g_inv[n][i];              // uniform per group
            const int c    = (ent >> 1) & (CC - 1);
            const int cnts = g_cnts[c];
            const int pc = cnts & 0xff;
            const int nc = (cnts >> 8) & 0xff;
            const int4* Lp = (const int4*)&g_lists[c][0];
            const int4 vp0 = Lp[0],  vp1 = Lp[1],  vp2 = Lp[2],  vp3 = Lp[3];
            const int4 vn0 = Lp[12], vn1 = Lp[13], vn2 = Lp[14], vn3 = Lp[15];

            // 16 pos gathers (coalesced across lanes), fmin tree (exact:
            // max fl(1-m) == fl(1 - min m), monotone single rounding)
            float mn;
            {
                float f0  = *(const float*)(mtb + vp0.x), f1  = *(const float*)(mtb + vp0.y);
                float f2  = *(const float*)(mtb + vp0.z), f3  = *(const float*)(mtb + vp0.w);
                float f4  = *(const float*)(mtb + vp1.x), f5  = *(const float*)(mtb + vp1.y);
                float f6  = *(const float*)(mtb + vp1.z), f7  = *(const float*)(mtb + vp1.w);
                float f8  = *(const float*)(mtb + vp2.x), f9  = *(const float*)(mtb + vp2.y);
                float f10 = *(const float*)(mtb + vp2.z), f11 = *(const float*)(mtb + vp2.w);
                float f12 = *(const float*)(mtb + vp3.x), f13 = *(const float*)(mtb + vp3.y);
                float f14 = *(const float*)(mtb + vp3.z), f15 = *(const float*)(mtb + vp3.w);
                float a0 = fminf(f0, f1),   a1 = fminf(f2, f3);
                float a2 = fminf(f4, f5),   a3 = fminf(f6, f7);
                float a4 = fminf(f8, f9),   a5 = fminf(f10, f11);
                float a6 = fminf(f12, f13), a7 = fminf(f14, f15);
                mn = fminf(fminf(fminf(a0, a1), fminf(a2, a3)),
                           fminf(fminf(a4, a5), fminf(a6, a7)));
            }
            for (int k = FLAT; k < pc; k++)            // rare tail (~3%)
                mn = fminf(mn, *(const float*)(mtb + g_lists[c][k]));

            // 16 neg gathers, fmax tree
            float mx;
            {
                float f0  = *(const float*)(mtb + vn0.x), f1  = *(const float*)(mtb + vn0.y);
                float f2  = *(const float*)(mtb + vn0.z), f3  = *(const float*)(mtb + vn0.w);
                float f4  = *(const float*)(mtb + vn1.x), f5  = *(const float*)(mtb + vn1.y);
                float f6  = *(const float*)(mtb + vn1.z), f7  = *(const float*)(mtb + vn1.w);
                float f8  = *(const float*)(mtb + vn2.x), f9  = *(const float*)(mtb + vn2.y);
                float f10 = *(const float*)(mtb + vn2.z), f11 = *(const float*)(mtb + vn2.w);
                float f12 = *(const float*)(mtb + vn3.x), f13 = *(const float*)(mtb + vn3.y);
                float f14 = *(const float*)(mtb + vn3.z), f15 = *(const float*)(mtb + vn3.w);
                float a0 = fmaxf(f0, f1),   a1 = fmaxf(f2, f3);
                float a2 = fmaxf(f4, f5),   a3 = fmaxf(f6, f7);
                float a4 = fmaxf(f8, f9),   a5 = fmaxf(f10, f11);
                float a6 = fmaxf(f12, f13), a7 = fmaxf(f14, f15);
                mx = fmaxf(fmaxf(fmaxf(a0, a1), fmaxf(a2, a3)),
                           fmaxf(fmaxf(a4, a5), fmaxf(a6, a7)));
            }
            for (int k = FLAT; k < nc; k++)
                mx = fmaxf(mx, *(const float*)(mtb + g_lists[c][LCAP + k]));

            // bmin = 1 - max(0, max_pos fl(1-m), max_neg m)
            const float bmax = fmaxf(1.0f - mn, mx);
            const unsigned bits = __float_as_uint(1.0f - bmax);  // in [0,1]
            if (ent & 1) atomicMax(&ub_s[b], bits);
            else         atomicMax(&lb_s[b], bits);
        }
    }
    __syncthreads();

    // finalize atom n's output column (cn==0: lb=0, ub=1 -> clamp(m)=m, exact)
    if (t < BB) {
        const float lb = __uint_as_float(lb_s[t]);
        const float ub = 1.0f - __uint_as_float(ub_s[t]);
        const float lo = fminf(lb, ub);
        const float hi = fmaxf(lb, ub);
        out[t * NC + col] = fmaxf(lo, fminf(hi, mval));
    }
}

extern "C" void kernel_launch(void* const* d_in, const int* in_sizes, int n_in,
                              void* d_out, int out_size)
{
    const float* preds    = (const float*)d_in[0];
    const float* pos_head = (const float*)d_in[1];
    const float* neg_head = (const float*)d_in[2];
    const float* pos_body = (const float*)d_in[3];
    const float* neg_body = (const float*)d_in[4];
    const int*   atoms    = (const int*)d_in[5];
    float* out = (float*)d_out;

    k_prep<<<NN, 128>>>(preds, pos_head, neg_head, pos_body, neg_body, atoms, out);
    k_atoms<<<NN, 512>>>(atoms, out);
}